// round 16
// baseline (speedup 1.0000x reference)
#include <cuda_runtime.h>
#include <cstdint>

#define H 128
#define W 128
#define NS 8
#define TY 32
#define SROWS (TY + 8)   // 40
#define SCOLS 136        // x_pad[c] = x[c-4], c in [0,136); 16B-aligned rows

// One (warp, s): 16 output rows x 4 cols/lane, sliding accumulator rotation.
// bp = &s_t[rowbase][xo + abase], abase = a - A4 (0 or 4), A4 = a & 3.
// Window value w[j'] for output col d, tap j: q[d + A4 + j] (compile-time).
template<int A4>
__device__ __forceinline__ void conv_s(const float* __restrict__ bp,
                                       const float* __restrict__ sF,
                                       float* __restrict__ ops)
{
    float F[25];
    #pragma unroll
    for (int t = 0; t < 25; ++t) F[t] = sF[t];

    float acc[16][4];
    #pragma unroll
    for (int k = 0; k < 20; ++k) {
        // 12 window values (8 if A4==0): aligned LDS.128
        float q[12];
        {
            float4 v0 = *(const float4*)(bp + k * SCOLS);
            float4 v1 = *(const float4*)(bp + k * SCOLS + 4);
            q[0]=v0.x; q[1]=v0.y; q[2]=v0.z; q[3]=v0.w;
            q[4]=v1.x; q[5]=v1.y; q[6]=v1.z; q[7]=v1.w;
            if (A4 > 0) {
                float4 v2 = *(const float4*)(bp + k * SCOLS + 8);
                q[8]=v2.x; q[9]=v2.y; q[10]=v2.z; q[11]=v2.w;
            }
        }
        #pragma unroll
        for (int y = 0; y < 16; ++y) {
            const int i = k - y;              // compile-time after unroll
            if (i >= 0 && i < 5) {
                #pragma unroll
                for (int d = 0; d < 4; ++d) {
                    float a = (i == 0) ? F[0] * q[d + A4]
                                       : fmaf(F[i * 5], q[d + A4], acc[y][d]);
                    #pragma unroll
                    for (int j = 1; j < 5; ++j)
                        a = fmaf(F[i * 5 + j], q[d + A4 + j], a);
                    acc[y][d] = a;
                }
            }
        }
        const int yd = k - 4;                 // row finished: store & retire
        if (yd >= 0 && yd < 16)
            *(float4*)(ops + yd * W) =
                make_float4(acc[yd][0], acc[yd][1], acc[yd][2], acc[yd][3]);
    }
}

__global__ void __launch_bounds__(128, 7)
shifted_conv_kernel(const float* __restrict__ tens,
                    const float* __restrict__ filters,
                    const int* __restrict__ shifts,
                    float* __restrict__ out)
{
    __shared__ __align__(16) float s_t[SROWS][SCOLS];   // 21.8 KB single copy
    __shared__ float s_f[NS * 25];
    __shared__ int   s_sh[NS * 2];

    const int n    = blockIdx.x;
    const int y0   = blockIdx.y * TY;   // 0,32,64,96
    const int tid  = threadIdx.x;
    const int lane = tid & 31;
    const int wrp  = tid >> 5;

    for (int i = tid; i < NS * 25; i += 128) s_f[i] = filters[i];
    if (tid < NS * 2) s_sh[tid] = shifts[tid];

    const float* inp = tens + (size_t)n * (H * W);
    for (int idx = tid; idx < SROWS * SCOLS; idx += 128) {
        int r  = idx / SCOLS;
        int c  = idx - r * SCOLS;
        int gy = y0 - 4 + r;
        int gx = c - 4;
        float v = 0.0f;
        if (gy >= 0 && gy < H && gx >= 0 && gx < W)
            v = inp[gy * W + gx];
        s_t[r][c] = v;
    }
    __syncthreads();

    // Warp s-split (proven in R15): warp handles 4 s over 16 rows.
    const int ybase = (wrp & 1) * 16;
    const int sbase = (wrp >> 1) * 4;
    const int xo    = 4 * lane;
    float* outw = out + (size_t)n * (NS * H * W)
                      + (size_t)(y0 + ybase) * W + xo;

    #pragma unroll 1
    for (int s = sbase; s < sbase + 4; ++s) {
        const int sy = s_sh[2 * s + 0];
        const int sx = s_sh[2 * s + 1];

        const int rowbase = ybase + 4 - sy;   // [ybase, ybase+4]
        const int a       = 4 - sx;           // [0, 4]
        const int A4r     = a & 3;
        const int abase   = a - A4r;          // 0 or 4 (a=4 -> A4=0, abase=4)

        const float* bp = &s_t[rowbase][xo + abase];
        const float* sF = &s_f[s * 25];
        float* ops = outw + (size_t)s * (H * W);

        switch (A4r) {                        // warp-uniform: no divergence
            case 0:  conv_s<0>(bp, sF, ops); break;
            case 1:  conv_s<1>(bp, sF, ops); break;
            case 2:  conv_s<2>(bp, sF, ops); break;
            default: conv_s<3>(bp, sF, ops); break;
        }
    }
}

extern "C" void kernel_launch(void* const* d_in, const int* in_sizes, int n_in,
                              void* d_out, int out_size)
{
    const float* tens    = (const float*)d_in[0];
    const float* filters = (const float*)d_in[1];
    const int*   shifts  = (const int*)d_in[2];
    float*       out     = (float*)d_out;

    dim3 grid(256, H / TY);   // 1024 blocks
    shifted_conv_kernel<<<grid, 128>>>(tens, filters, shifts, out);
}

// round 17
// speedup vs baseline: 1.1952x; 1.1952x over previous
#include <cuda_runtime.h>
#include <cstdint>

#define H 128
#define W 128
#define NS 8
#define TY 16
#define SROWS (TY + 8)    // 24
#define SCOLS 136         // x_pad[c] = x[c-4], c in [0,136)
#define EC    (SCOLS / 2) // 68 entries per parity row

__global__ void __launch_bounds__(128, 7)
shifted_conv_kernel(const float* __restrict__ tens,
                    const float* __restrict__ filters,
                    const int* __restrict__ shifts,
                    float* __restrict__ out)
{
    // Parity-deinterleaved tile, two copies per parity shifted by one entry:
    //   s_p[p][0][r][i] = x_pad[r][2i+p]
    //   s_p[p][1][r][i] = x_pad[r][2i+p+2]
    __shared__ __align__(16) float s_p[2][2][SROWS][EC];   // 26.1 KB
    __shared__ float s_f[NS * 25];
    __shared__ int   s_sh[NS * 2];

    const int n    = blockIdx.x;
    const int y0   = blockIdx.y * TY;   // 0..112 step 16
    const int tid  = threadIdx.x;
    const int lane = tid & 31;
    const int wrp  = tid >> 5;

    for (int i = tid; i < NS * 25; i += 128) s_f[i] = filters[i];
    if (tid < NS * 2) s_sh[tid] = shifts[tid];

    const float* inp = tens + (size_t)n * (H * W);
    for (int idx = tid; idx < SROWS * SCOLS; idx += 128) {
        int r  = idx / SCOLS;
        int c  = idx - r * SCOLS;
        int gy = y0 - 4 + r;
        int gx = c - 4;
        float v = 0.0f;
        if (gy >= 0 && gy < H && gx >= 0 && gx < W)
            v = inp[gy * W + gx];
        int p = c & 1, e = c >> 1;
        s_p[p][0][r][e] = v;
        if (e > 0) s_p[p][1][r][e - 1] = v;
    }
    for (int r = tid; r < SROWS; r += 128) {   // copy1 tails: x_pad[136/137]=0
        s_p[0][1][r][EC - 1] = 0.0f;
        s_p[1][1][r][EC - 1] = 0.0f;
    }
    __syncthreads();

    // Warp s-split: warp handles 4 s-groups over 8 output rows.
    const int ybase = (wrp & 1) * 8;
    const int sbase = (wrp >> 1) * 4;
    const int xo    = 4 * lane;
    float* outw = out + (size_t)n * (NS * H * W)
                      + (size_t)(y0 + ybase) * W + xo;

    #pragma unroll 1
    for (int s = sbase; s < sbase + 4; ++s) {
        const int sy = s_sh[2 * s + 0];
        const int sx = s_sh[2 * s + 1];

        // Scalar filter taps: 25 plain registers.
        float F[25];
        #pragma unroll
        for (int t = 0; t < 25; ++t) F[t] = s_f[s * 25 + t];

        const int rowbase = ybase + 4 - sy;   // [0, 12]
        const int a       = 4 - sx;           // [0, 4]

        // Window w[t] = x_pad[xo + a + t], t in [0,8). Four pair loads give
        // the whole window: t in {0,1,4,5} -> (w_t, w_{t+2}).
        // Pair t: parity p=(a+t)&1, entry start h=(a+t-p)>>1; copy h&1 makes
        // the LDS.64 8B-aligned. Runtime pointers, compile-time pattern.
        const float* bp[4];
        {
            const int tt[4] = {0, 1, 4, 5};
            #pragma unroll
            for (int u = 0; u < 4; ++u) {
                int t = tt[u];
                int p = (a + t) & 1;
                int h = (a + t - p) >> 1;
                bp[u] = &s_p[p][h & 1][rowbase][2 * lane + (h & ~1)];
            }
        }

        float* ops = outw + (size_t)s * (H * W);

        // Sliding rotation: 12 input rows -> 8 output rows; row y live for
        // k in [y, y+4]; stored right after its last tap (<=5 rows live).
        float acc[8][4];
        #pragma unroll
        for (int k = 0; k < 12; ++k) {
            float2 p0 = *(const float2*)(bp[0] + k * EC);  // (w0, w2)
            float2 p1 = *(const float2*)(bp[1] + k * EC);  // (w1, w3)
            float2 p4 = *(const float2*)(bp[2] + k * EC);  // (w4, w6)
            float2 p5 = *(const float2*)(bp[3] + k * EC);  // (w5, w7)
            float w[8];
            w[0] = p0.x; w[2] = p0.y;
            w[1] = p1.x; w[3] = p1.y;
            w[4] = p4.x; w[6] = p4.y;
            w[5] = p5.x; w[7] = p5.y;

            #pragma unroll
            for (int y = 0; y < 8; ++y) {
                const int i = k - y;           // compile-time after unroll
                if (i >= 0 && i < 5) {
                    #pragma unroll
                    for (int d = 0; d < 4; ++d) {
                        float acc0 = (i == 0) ? F[0] * w[d]
                                              : fmaf(F[i * 5], w[d], acc[y][d]);
                        #pragma unroll
                        for (int j = 1; j < 5; ++j)
                            acc0 = fmaf(F[i * 5 + j], w[d + j], acc0);
                        acc[y][d] = acc0;
                    }
                }
            }
            const int yd = k - 4;              // row finished: store & retire
            if (yd >= 0 && yd < 8)
                *(float4*)(ops + yd * W) =
                    make_float4(acc[yd][0], acc[yd][1], acc[yd][2], acc[yd][3]);
        }
    }
}

extern "C" void kernel_launch(void* const* d_in, const int* in_sizes, int n_in,
                              void* d_out, int out_size)
{
    const float* tens    = (const float*)d_in[0];
    const float* filters = (const float*)d_in[1];
    const int*   shifts  = (const int*)d_in[2];
    float*       out     = (float*)d_out;

    dim3 grid(256, H / TY);   // 2048 blocks
    shifted_conv_kernel<<<grid, 128>>>(tens, filters, shifts, out);
}